// round 16
// baseline (speedup 1.0000x reference)
#include <cuda_runtime.h>
#include <cuda_fp16.h>
#include <mma.h>
#include <cstdint>

using namespace nvcuda;

#define Bn 16
#define Tn 12
#define BT 192          // B*T
#define Nn 325
#define Dd 64
#define Hh 4
#define Ee 2600
#define ET (Ee + Nn)    // 2925 edges incl. self loops
#define NBT (Nn * BT)   // 62400 (n,bt) pairs
#define MAXDEG 64

typedef unsigned long long ull;

// ---------------- packed f32x2 helpers ----------------
__device__ __forceinline__ void ffma2(ull& d, ull a, ull b) {
    asm("fma.rn.f32x2 %0, %1, %2, %0;" : "+l"(d) : "l"(a), "l"(b));
}
__device__ __forceinline__ ull pack2(float lo, float hi) {
    ull r; asm("mov.b64 %0, {%1,%2};" : "=l"(r) : "f"(lo), "f"(hi)); return r;
}
__device__ __forceinline__ void unpack2(float& lo, float& hi, ull v) {
    asm("mov.b64 {%0,%1}, %2;" : "=f"(lo), "=f"(hi) : "l"(v));
}
__device__ __forceinline__ uint32_t smem_u32(const void* p) {
    uint32_t a;
    asm("{.reg .u64 t; cvta.to.shared.u64 t, %1; cvt.u32.u64 %0, t;}" : "=r"(a) : "l"(p));
    return a;
}
#define CP_CG16(dst_u32, src_ptr) \
    asm volatile("cp.async.cg.shared.global [%0], [%1], 16;" \
                 :: "r"(dst_u32), "l"(src_ptr) : "memory")
#define CP_CA16(dst_u32, src_ptr) \
    asm volatile("cp.async.ca.shared.global [%0], [%1], 16;" \
                 :: "r"(dst_u32), "l"(src_ptr) : "memory")
#define CP_COMMIT() asm volatile("cp.async.commit_group;" ::: "memory")

// ---------------- device scratch ----------------
__device__ __align__(16) float g_wsrc[Hh * Dd];
__device__ __align__(16) float g_wdst[Hh * Dd];
__device__ __align__(16) float g_asrc[NBT * Hh];
__device__ __align__(16) float g_adst[NBT * Hh];
__device__ int g_deg[Nn];
__device__ int g_esrc2[Nn * MAXDEG];                       // fixed-stride edge lists
__device__ __align__(16) __half g_Af[(size_t)NBT * 256];   // fp16 A, 32MB
__device__ __align__(16) __half g_Bf[256 * 64];            // B fp16, [k][f], 1/H folded

// ---------------- K0: setup (blocks 0..324 = per-node CSR, block 325 = weights) ----
// edge_index may be int32 or int64 (JAX x64-config). Probe: int64 => odd words
// are all zero (values < 325); int32 => essentially never all zero.
__global__ void k_setup(const int* __restrict__ ew,
                        const float* __restrict__ W,
                        const float* __restrict__ att_src,
                        const float* __restrict__ att_dst) {
    const unsigned full = 0xffffffffu;
    int b = blockIdx.x;
    int tid = threadIdx.x;
    if (b == Nn) {
        // ---- weight prep ----
        if (tid < 256) {
            int h = tid >> 6, d = tid & 63;
            float s1 = 0.f, s2 = 0.f;
            #pragma unroll 8
            for (int f = 0; f < 64; f++) {
                float w = W[(d * Hh + h) * 64 + f];
                s1 += w * att_src[h * 64 + f];
                s2 += w * att_dst[h * 64 + f];
            }
            g_wsrc[tid] = s1;
            g_wdst[tid] = s2;
        }
        for (int i = tid; i < 256 * 64; i += blockDim.x) {
            int k = i >> 6, f = i & 63;
            int h = k >> 6, d = k & 63;
            g_Bf[i] = __float2half_rn(W[(d * Hh + h) * 64 + f] * 0.25f);
        }
        return;
    }
    // ---- per-node CSR: warp 0 scans all edges in order (deterministic) ----
    if (tid >= 32) return;
    int lane = tid;
    // dtype probe on first 64 odd words
    int nz = 0;
    #pragma unroll
    for (int i = 0; i < 2; i++)
        if (ew[2 * (lane + 32 * i) + 1] != 0) nz = 1;
    int is32 = (__ballot_sync(full, nz) != 0);
    int cnt = 0;
    for (int base = 0; base < ET; base += 32) {
        int i = base + lane;
        int src = 0, dst = -1;
        if (i < ET) {
            if (i < Ee) {
                if (is32) { src = ew[i];     dst = ew[Ee + i]; }
                else      { src = ew[2 * i]; dst = ew[2 * (Ee + i)]; }
            } else {
                src = i - Ee;
                dst = i - Ee;
            }
        }
        unsigned bal = __ballot_sync(full, dst == b);
        if (dst == b) {
            int pos = cnt + __popc(bal & ((1u << lane) - 1));
            g_esrc2[b * MAXDEG + pos] = src;
        }
        cnt += __popc(bal);
    }
    if (lane == 0) g_deg[b] = cnt;
}

// ---------------- K1: attention logits, warp per (n,bt) ----------------
__global__ __launch_bounds__(256) void k_alpha(const float* __restrict__ x) {
    __shared__ float sw[512];
    int tid = threadIdx.x;
    sw[tid] = g_wsrc[tid];
    sw[256 + tid] = g_wdst[tid];
    __syncthreads();
    int gid = blockIdx.x * 8 + (tid >> 5);
    int lane = tid & 31;
    int n = gid / BT, bt = gid % BT;
    float2 xv = ((const float2*)(x + ((size_t)bt * Nn + n) * 64))[lane];
    float p[8];
    #pragma unroll
    for (int h = 0; h < 4; h++) {
        p[h]     = xv.x * sw[h * 64 + 2 * lane]       + xv.y * sw[h * 64 + 2 * lane + 1];
        p[4 + h] = xv.x * sw[256 + h * 64 + 2 * lane] + xv.y * sw[256 + h * 64 + 2 * lane + 1];
    }
    #pragma unroll
    for (int o = 16; o; o >>= 1) {
        #pragma unroll
        for (int j = 0; j < 8; j++) p[j] += __shfl_xor_sync(0xffffffffu, p[j], o);
    }
    int base = gid * 4;
    if (lane < 4) g_asrc[base + lane] = p[lane];
    else if (lane < 8) g_adst[base + lane - 4] = p[lane];
}

// ---------------- K2: segment softmax + aggregation -> fp16 A ----------------
__device__ __forceinline__ float lrelu(float v) { return v >= 0.f ? v : 0.2f * v; }

__global__ __launch_bounds__(256) void k_agg(const float* __restrict__ x) {
    __shared__ int s_src[8][32];
    __shared__ __align__(16) ull s_cf[8][32][4];   // dup'd coef pairs {c,c}
    const unsigned full = 0xffffffffu;
    int tid = threadIdx.x;
    int w = tid >> 5, lane = tid & 31;
    int gid = blockIdx.x * 8 + w;
    int n = gid / BT, bt = gid % BT;
    int deg = g_deg[n];
    const int* elist = g_esrc2 + n * MAXDEG;
    float4 adv = *(const float4*)(g_adst + gid * 4);

    float sm[4] = {0.f, 0.f, 0.f, 0.f};
    float c0[4] = {0.f, 0.f, 0.f, 0.f};
    int s0 = 0;
    for (int e = lane; e < deg; e += 32) {
        int s = elist[e];
        float4 av = *(const float4*)(g_asrc + (s * BT + bt) * 4);
        float v0 = __expf(lrelu(av.x + adv.x));
        float v1 = __expf(lrelu(av.y + adv.y));
        float v2 = __expf(lrelu(av.z + adv.z));
        float v3 = __expf(lrelu(av.w + adv.w));
        sm[0] += v0; sm[1] += v1; sm[2] += v2; sm[3] += v3;
        if (e == lane) { s0 = s; c0[0] = v0; c0[1] = v1; c0[2] = v2; c0[3] = v3; }
    }
    #pragma unroll
    for (int o = 16; o; o >>= 1) {
        #pragma unroll
        for (int h = 0; h < 4; h++) sm[h] += __shfl_xor_sync(full, sm[h], o);
    }
    float inv[4];
    #pragma unroll
    for (int h = 0; h < 4; h++) inv[h] = 1.f / (sm[h] + 1e-16f);
    if (lane < deg) {
        s_src[w][lane] = s0;
        #pragma unroll
        for (int h = 0; h < 4; h++) {
            float c = c0[h] * inv[h];
            s_cf[w][lane][h] = pack2(c, c);
        }
    }
    __syncwarp();

    ull acc0 = 0, acc1 = 0, acc2 = 0, acc3 = 0;
    const float* xb = x + (size_t)bt * (Nn * 64);
    int jm = deg < 32 ? deg : 32;
    int j = 0;
    for (; j + 4 <= jm; j += 4) {          // 4-way unroll: MLP on L2-bound x gathers
        int sA = s_src[w][j], sB = s_src[w][j + 1];
        int sC = s_src[w][j + 2], sD = s_src[w][j + 3];
        ull x1 = *(const ull*)(xb + sA * 64 + 2 * lane);
        ull x2 = *(const ull*)(xb + sB * 64 + 2 * lane);
        ull x3 = *(const ull*)(xb + sC * 64 + 2 * lane);
        ull x4 = *(const ull*)(xb + sD * 64 + 2 * lane);
        ulonglong2 a1 = *(const ulonglong2*)&s_cf[w][j][0];
        ulonglong2 b1 = *(const ulonglong2*)&s_cf[w][j][2];
        ulonglong2 a2 = *(const ulonglong2*)&s_cf[w][j + 1][0];
        ulonglong2 b2 = *(const ulonglong2*)&s_cf[w][j + 1][2];
        ulonglong2 a3 = *(const ulonglong2*)&s_cf[w][j + 2][0];
        ulonglong2 b3 = *(const ulonglong2*)&s_cf[w][j + 2][2];
        ulonglong2 a4 = *(const ulonglong2*)&s_cf[w][j + 3][0];
        ulonglong2 b4 = *(const ulonglong2*)&s_cf[w][j + 3][2];
        ffma2(acc0, x1, a1.x); ffma2(acc1, x1, a1.y);
        ffma2(acc2, x1, b1.x); ffma2(acc3, x1, b1.y);
        ffma2(acc0, x2, a2.x); ffma2(acc1, x2, a2.y);
        ffma2(acc2, x2, b2.x); ffma2(acc3, x2, b2.y);
        ffma2(acc0, x3, a3.x); ffma2(acc1, x3, a3.y);
        ffma2(acc2, x3, b3.x); ffma2(acc3, x3, b3.y);
        ffma2(acc0, x4, a4.x); ffma2(acc1, x4, a4.y);
        ffma2(acc2, x4, b4.x); ffma2(acc3, x4, b4.y);
    }
    for (; j < jm; j++) {
        int src = s_src[w][j];
        ulonglong2 cA = *(const ulonglong2*)&s_cf[w][j][0];
        ulonglong2 cB = *(const ulonglong2*)&s_cf[w][j][2];
        ull xv = *(const ull*)(xb + src * 64 + 2 * lane);
        ffma2(acc0, xv, cA.x);
        ffma2(acc1, xv, cA.y);
        ffma2(acc2, xv, cB.x);
        ffma2(acc3, xv, cB.y);
    }
    for (int jj = 32; jj < deg; jj++) {    // rare: degree > 32
        int src = elist[jj];
        float4 av = *(const float4*)(g_asrc + (src * BT + bt) * 4);
        float cc0 = __expf(lrelu(av.x + adv.x)) * inv[0];
        float cc1 = __expf(lrelu(av.y + adv.y)) * inv[1];
        float cc2 = __expf(lrelu(av.z + adv.z)) * inv[2];
        float cc3 = __expf(lrelu(av.w + adv.w)) * inv[3];
        ull xv = *(const ull*)(xb + src * 64 + 2 * lane);
        ffma2(acc0, xv, pack2(cc0, cc0));
        ffma2(acc1, xv, pack2(cc1, cc1));
        ffma2(acc2, xv, pack2(cc2, cc2));
        ffma2(acc3, xv, pack2(cc3, cc3));
    }
    // store fp16 A: half2 index, k = h*64 + 2*lane
    size_t base = (size_t)gid * 128 + lane;
    __half2* af = ((__half2*)g_Af) + base;
    float e, o;
    unpack2(e, o, acc0); af[0]  = __floats2half2_rn(e, o);
    unpack2(e, o, acc1); af[32] = __floats2half2_rn(e, o);
    unpack2(e, o, acc2); af[64] = __floats2half2_rn(e, o);
    unpack2(e, o, acc3); af[96] = __floats2half2_rn(e, o);
}

// ---------------- K3: fp16 WMMA GEMM, cp.async double-buffered + fused LN ----------------
// Block: 96 rows x 64 cols, K=256 in 4 chunks of 64. 192 threads = 6 warps,
// warp = 16 rows. D = A*B, f32 accum, single fp16 B term. 650 blocks exact.
#define GBM 96
#define LDA 72
#define A_BUF (GBM * LDA)                 // 6912 half
#define B_BUF (64 * LDA)                  // 4608 half
#define OFF_A(b)  ((b) * A_BUF)
#define OFF_B(b)  (2 * A_BUF + (b) * B_BUF)
#define SM_HALF (2 * A_BUF + 2 * B_BUF)   // 23040 half = 46080 B (static)

__device__ __forceinline__ void stage_chunk(uint32_t sb, int buf,
                                            int r0, int kc, int tid) {
    // A: 768 x 16B for 96 rows x 64 k (fp16)
    #pragma unroll
    for (int i = 0; i < 4; i++) {
        int idx = tid + 192 * i;
        int row = idx >> 3;
        int k8 = (idx & 7) * 8;
        const __half* src = g_Af + (size_t)(r0 + row) * 256 + kc + k8;
        uint32_t dst = sb + (OFF_A(buf) + row * LDA + k8) * 2;
        CP_CG16(dst, src);
    }
    // B: 512 x 16B for 64 k x 64 f
    #pragma unroll
    for (int i = 0; i < 3; i++) {
        int idx = tid + 192 * i;
        if (idx < 512) {
            int row = idx >> 3;
            int f0 = (idx & 7) * 8;
            const __half* src = g_Bf + (size_t)(kc + row) * 64 + f0;
            uint32_t dst = sb + (OFF_B(buf) + row * LDA + f0) * 2;
            CP_CA16(dst, src);
        }
    }
    CP_COMMIT();
}

__global__ __launch_bounds__(192) void k_gemm(const float* __restrict__ x,
                                              const float* __restrict__ bias,
                                              const float* __restrict__ gamma,
                                              const float* __restrict__ beta,
                                              float* __restrict__ out) {
    __shared__ __align__(16) __half sm_h[SM_HALF];
    uint32_t sb = smem_u32(sm_h);
    float* CS = (float*)sm_h;                 // epilogue alias (24576B <= 46080B)
    int tid = threadIdx.x;
    int w = tid >> 5, lane = tid & 31;
    int r0 = blockIdx.x * GBM;

    wmma::fragment<wmma::accumulator, 16, 16, 16, float> acc[4];
    #pragma unroll
    for (int c = 0; c < 4; c++) wmma::fill_fragment(acc[c], 0.f);

    stage_chunk(sb, 0, r0, 0, tid);

    #pragma unroll 1
    for (int c = 0; c < 4; c++) {
        int cur = c & 1;
        if (c < 3) {
            stage_chunk(sb, 1 - cur, r0, (c + 1) * 64, tid);
            asm volatile("cp.async.wait_group 1;" ::: "memory");
        } else {
            asm volatile("cp.async.wait_group 0;" ::: "memory");
        }
        __syncthreads();

        const __half* As = sm_h + OFF_A(cur);
        const __half* Bs = sm_h + OFF_B(cur);
        #pragma unroll
        for (int ks = 0; ks < 4; ks++) {
            wmma::fragment<wmma::matrix_a, 16, 16, 16, half, wmma::row_major> fa;
            wmma::load_matrix_sync(fa, As + (w * 16) * LDA + ks * 16, LDA);
            #pragma unroll
            for (int cc = 0; cc < 4; cc++) {
                wmma::fragment<wmma::matrix_b, 16, 16, 16, half, wmma::row_major> fb;
                wmma::load_matrix_sync(fb, Bs + (ks * 16) * LDA + cc * 16, LDA);
                wmma::mma_sync(acc[cc], fa, fb, acc[cc]);
            }
        }
        __syncthreads();
    }

    // ---- stage C into shared ----
    #pragma unroll
    for (int c = 0; c < 4; c++)
        wmma::store_matrix_sync(CS + (w * 16) * 64 + c * 16, acc[c], 64, wmma::mem_row_major);
    __syncthreads();

    // ---- epilogue: bias + residual + LayerNorm, warp per row, 16 rows/warp ----
    float2 bi = ((const float2*)bias)[lane];
    float2 ga = ((const float2*)gamma)[lane];
    float2 be = ((const float2*)beta)[lane];
    const unsigned full = 0xffffffffu;
    #pragma unroll
    for (int it = 0; it < 16; it++) {
        int row = w * 16 + it;
        int r = r0 + row;
        int n = r / BT, bt = r % BT;
        size_t xo = ((size_t)bt * Nn + n) * 64;
        float2 cc = *(const float2*)(CS + row * 64 + lane * 2);
        float2 xv = *(const float2*)(x + xo + lane * 2);
        float yx = xv.x + cc.x + bi.x;
        float yy = xv.y + cc.y + bi.y;
        float s = yx + yy;
        float s2 = yx * yx + yy * yy;
        #pragma unroll
        for (int o = 16; o; o >>= 1) {
            s += __shfl_xor_sync(full, s, o);
            s2 += __shfl_xor_sync(full, s2, o);
        }
        float mu = s * (1.f / 64.f);
        float var = s2 * (1.f / 64.f) - mu * mu;
        float rstd = rsqrtf(var + 1e-5f);
        float2 o2;
        o2.x = (yx - mu) * rstd * ga.x + be.x;
        o2.y = (yy - mu) * rstd * ga.y + be.y;
        *(float2*)(out + xo + lane * 2) = o2;
    }
}

// ---------------- launcher ----------------
extern "C" void kernel_launch(void* const* d_in, const int* in_sizes, int n_in,
                              void* d_out, int out_size) {
    const float* x        = (const float*)d_in[0];
    const float* W        = (const float*)d_in[1];
    const float* att_src  = (const float*)d_in[2];
    const float* att_dst  = (const float*)d_in[3];
    const float* bias     = (const float*)d_in[4];
    const float* gamma    = (const float*)d_in[5];
    const float* beta     = (const float*)d_in[6];
    const int*   edge     = (const int*)d_in[7];
    float* out = (float*)d_out;

    k_setup<<<Nn + 1, 256>>>(edge, W, att_src, att_dst);
    k_alpha<<<NBT / 8, 256>>>(x);
    k_agg<<<NBT / 8, 256>>>(x);
    k_gemm<<<NBT / GBM, 192>>>(x, bias, gamma, beta, out);
}